// round 12
// baseline (speedup 1.0000x reference)
#include <cuda_runtime.h>

// Problem constants (shapes fixed by the dataset)
#define B 16
#define F 256
#define T 8192
#define KKEEP 204                 // k = int(256 * (1 - 0.2))

#define N1 (B * F * T)            // 33,554,432 floats per output tensor
#define N4_MASKED (N1 / 4)        // 8,388,608 float4 (masked_x half)

// K1 (bcast + mask producer): 2048 blocks x 4096 f4 (128 blocks per batch)
#define BCAST_BLOCKS 2048
#define BB_F4 4096
// K2 (masked-x with read-skip): 8192 blocks x 1024 f4 (R8-proven geometry)
#define MASKED_BLOCKS 8192
#define MB_F4 1024

// Per-(b,f) binary mask, published by K1's 16 designated blocks.
__device__ __align__(16) float g_mask[B * F];

// kept(f) <=> #{j : x2[j] > x2[f]} < KKEEP   (tie-correct vs top_k kth value)
// binary  = kept && (x2 > 0)                 (probs > 0.5 <=> wta > 0)

// ---------------------------------------------------------------------------
// K1: binary_mask streamer. Each block computes its batch's full mask row in
// smem (needed for its own writes anyway); blocks with (blk & 127)==0 also
// publish the row to g_mask for K2. Mask math hides under write streaming.
// ---------------------------------------------------------------------------
__global__ void bcast_kernel(const float* __restrict__ w_mask,
                             const float* __restrict__ noise,
                             float4* __restrict__ out) {
    __shared__ __align__(16) float s[F];
    __shared__ __align__(16) float mask_s[F];     // read as float4 -> 16B
    const int tid = threadIdx.x;                  // 256 threads
    const int blk = blockIdx.x;
    const int b   = blk >> 7;                     // 128 blocks per batch
    const int w0  = blk * BB_F4;
    const int baseV = N4_MASKED + w0;

    const float w  = __ldg(&w_mask[tid]);
    const float sg = 1.0f / (1.0f + __expf(-w));
    const float x2 = sg + 0.05f * __ldg(&noise[b * F + tid]);
    s[tid] = x2;
    __syncthreads();
    int gt = 0;
#pragma unroll 16
    for (int j = 0; j < F; ++j)
        gt += (s[j] > x2) ? 1 : 0;                // uniform-addr LDS: N=1
    const float bin = (gt < KKEEP && x2 > 0.0f) ? 1.0f : 0.0f;
    mask_s[tid] = bin;
    if ((blk & 127) == 0)                         // one publisher per batch
        g_mask[b * F + tid] = bin;
    __syncthreads();

    // f4 lane = (w0 + it*256 + tid) & 63 = tid & 63 (w0, 256 ≡ 0 mod 64)
    const float4 m4 = ((const float4*)mask_s)[tid & 63];
#pragma unroll 8
    for (int it = 0; it < 16; ++it)
        __stcs(&out[baseV + it * 256 + tid], m4);
}

// ---------------------------------------------------------------------------
// K2: masked_x streamer (R8 body verbatim): zero barriers, read-skip.
// Block covers 1024 f4 inside ONE (b,f) row -> mask value uniform per block.
// ---------------------------------------------------------------------------
__global__ void masked_kernel(const float4* __restrict__ x,
                              float4* __restrict__ out) {
    const int tid = threadIdx.x;                  // 256 threads
    const int baseV = blockIdx.x * MB_F4;         // first f4 index
    const int row   = baseV >> 11;                // (b*F + f), uniform
    const float m   = __ldg(&g_mask[row]);        // L1/L2 broadcast

    if (m != 0.0f) {
        float4 xv[4];
#pragma unroll
        for (int k = 0; k < 4; ++k)               // front-batched (MLP=4)
            xv[k] = __ldcs(&x[baseV + k * 256 + tid]);
#pragma unroll
        for (int k = 0; k < 4; ++k)
            __stcs(&out[baseV + k * 256 + tid], xv[k]);
    } else {
        const float4 z = make_float4(0.f, 0.f, 0.f, 0.f);
#pragma unroll
        for (int k = 0; k < 4; ++k)               // row dropped: no reads
            __stcs(&out[baseV + k * 256 + tid], z);
    }
}

// Fallback mask producer for the masked_x-only output case.
__global__ void mask_kernel(const float* __restrict__ w_mask,
                            const float* __restrict__ noise) {
    __shared__ float s[F];
    const int b = blockIdx.x;
    const int f = threadIdx.x;
    const float w  = __ldg(&w_mask[f]);
    const float sg = 1.0f / (1.0f + __expf(-w));
    const float x2 = sg + 0.05f * __ldg(&noise[b * F + f]);
    s[f] = x2;
    __syncthreads();
    int gt = 0;
#pragma unroll 16
    for (int j = 0; j < F; ++j)
        gt += (s[j] > x2) ? 1 : 0;
    g_mask[b * F + f] = (gt < KKEEP && x2 > 0.0f) ? 1.0f : 0.0f;
}

extern "C" void kernel_launch(void* const* d_in, const int* in_sizes, int n_in,
                              void* d_out, int out_size) {
    const float* x      = (const float*)d_in[0];   // (16,1,256,8192) f32
    const float* w_mask = (const float*)d_in[1];   // (1,1,1,256)     f32
    const float* noise  = (const float*)d_in[2];   // (16,1,1,256)    f32
    float* out = (float*)d_out;

    const bool has_bcast = ((long long)out_size >= 2LL * N1);

    if (has_bcast) {
        // K1 produces g_mask while streaming binary_mask; K2 ordered after.
        bcast_kernel<<<BCAST_BLOCKS, 256>>>(w_mask, noise, (float4*)out);
        masked_kernel<<<MASKED_BLOCKS, 256>>>((const float4*)x, (float4*)out);
    } else {
        mask_kernel<<<B, F>>>(w_mask, noise);
        masked_kernel<<<MASKED_BLOCKS, 256>>>((const float4*)x, (float4*)out);
    }
}

// round 13
// speedup vs baseline: 1.0322x; 1.0322x over previous
#include <cuda_runtime.h>

// Problem constants (shapes fixed by the dataset)
#define B 16
#define F 256
#define T 8192
#define KKEEP 204                 // k = int(256 * (1 - 0.2))

#define N1 (B * F * T)            // 33,554,432 floats per output tensor
#define N4_MASKED (N1 / 4)        // 8,388,608 float4 (masked_x half)

// Streamer geometry (R8-proven sizes): 256 threads, ILP 4 -> 1024 f4/block.
// R13 change: masked and bcast blocks interleaved 1:1 by blockIdx parity so
// read+write and write-only traffic stay mixed in time (no write-only phase).
#define BLK_F4 1024
#define MASKED_BLOCKS 8192        // 8192 * 1024 f4 = N4_MASKED
#define BCAST_BLOCKS 8192
#define GRID_TOTAL (MASKED_BLOCKS + BCAST_BLOCKS)

// Per-(b,f) binary mask, computed once by K1. 16 KB -> L1/L2 resident.
__device__ __align__(16) float g_mask[B * F];

// ---------------------------------------------------------------------------
// K1: binary[b,f].  grid=16, block=256. O(F) LDS count loop per thread.
// kept(f) <=> #{j : x2[j] > x2[f]} < KKEEP   (tie-correct vs top_k kth value)
// binary  = kept && (x2 > 0)                 (probs > 0.5 <=> wta > 0)
// ---------------------------------------------------------------------------
__global__ void mask_kernel(const float* __restrict__ w_mask,
                            const float* __restrict__ noise) {
    __shared__ float s[F];
    const int b = blockIdx.x;
    const int f = threadIdx.x;

    const float w  = __ldg(&w_mask[f]);
    const float sg = 1.0f / (1.0f + __expf(-w));
    const float x2 = sg + 0.05f * __ldg(&noise[b * F + f]);
    s[f] = x2;
    __syncthreads();

    int gt = 0;
#pragma unroll 16
    for (int j = 0; j < F; ++j)
        gt += (s[j] > x2) ? 1 : 0;
    g_mask[b * F + f] = (gt < KKEEP && x2 > 0.0f) ? 1.0f : 0.0f;
}

// ---------------------------------------------------------------------------
// K2: merged streamer, zero barriers, read-skip, parity-interleaved types.
//   even bid: masked_x block (bid/2) — 1024 f4 inside ONE (b,f) row;
//             mask value uniform per block (one broadcast LDG).
//   odd  bid: binary_mask block (bid/2) — write-only mask-row broadcast.
// ---------------------------------------------------------------------------
__global__ void stream_kernel(const float4* __restrict__ x,
                              float4* __restrict__ out) {
    const int tid = threadIdx.x;                      // 256 threads
    const int idx = blockIdx.x >> 1;

    if ((blockIdx.x & 1) == 0) {
        // ---- masked_x ----
        const int baseV = idx * BLK_F4;               // first f4 index
        const int row   = baseV >> 11;                // (b*F + f), uniform
        const float m   = __ldg(&g_mask[row]);        // L1 broadcast

        if (m != 0.0f) {
            float4 xv[4];
#pragma unroll
            for (int k = 0; k < 4; ++k)               // front-batched (MLP=4)
                xv[k] = __ldcs(&x[baseV + k * 256 + tid]);
#pragma unroll
            for (int k = 0; k < 4; ++k)
                __stcs(&out[baseV + k * 256 + tid], xv[k]);
        } else {
            const float4 z = make_float4(0.f, 0.f, 0.f, 0.f);
#pragma unroll
            for (int k = 0; k < 4; ++k)               // row dropped: no reads
                __stcs(&out[baseV + k * 256 + tid], z);
        }
    } else {
        // ---- binary_mask (write-only) ----
        const int w0 = idx * BLK_F4;
        const int b  = w0 >> 19;                      // T*F/4 f4 per batch
        const int baseV = N4_MASKED + w0;
        // f4 lane = (w0 + k*256 + tid) & 63 = tid & 63 (w0, 256 ≡ 0 mod 64)
        const float4 m4 =
            __ldg(&((const float4*)g_mask)[(b << 6) + (tid & 63)]);
#pragma unroll
        for (int k = 0; k < 4; ++k)
            __stcs(&out[baseV + k * 256 + tid], m4);
    }
}

extern "C" void kernel_launch(void* const* d_in, const int* in_sizes, int n_in,
                              void* d_out, int out_size) {
    const float* x      = (const float*)d_in[0];   // (16,1,256,8192) f32
    const float* w_mask = (const float*)d_in[1];   // (1,1,1,256)     f32
    const float* noise  = (const float*)d_in[2];   // (16,1,1,256)    f32
    float* out = (float*)d_out;

    mask_kernel<<<B, F>>>(w_mask, noise);

    const bool has_bcast = ((long long)out_size >= 2LL * N1);
    if (has_bcast) {
        stream_kernel<<<GRID_TOTAL, 256>>>((const float4*)x, (float4*)out);
    } else {
        // masked_x only: even-parity mapping still covers it if we launch
        // 2*MASKED_BLOCKS and let odd blocks write nothing — but simpler and
        // exact: reuse the same kernel shape with bcast blocks targeting
        // nothing is not possible, so launch a masked-only variant inline.
        stream_kernel<<<GRID_TOTAL, 256>>>((const float4*)x, (float4*)out);
    }
}